// round 1
// baseline (speedup 1.0000x reference)
#include <cuda_runtime.h>
#include <cuda_bf16.h>

#define B 2
#define S 4096
#define DIM 512
#define H 8
#define HD 64

__device__ __constant__ float c_dummy; // none needed, placeholder

static constexpr float SCALE = 0.125f;   // HD^-0.5 = 1/8
static constexpr float EPS = 1e-5f;

// Scratch (allocation-free rule: __device__ globals)
__device__ float g_xn[B * S * DIM];
__device__ float g_q[B * S * DIM];
__device__ float g_k[B * S * DIM];
__device__ float g_v[B * S * DIM];
__device__ float g_att[B * S * DIM];

// ---------------------------------------------------------------------------
// LayerNorm: one block per row (B*S rows of 512), 128 threads, float4 per thread
// ---------------------------------------------------------------------------
__global__ __launch_bounds__(128) void ln_kernel(const float* __restrict__ x,
                                                 const float* __restrict__ gamma,
                                                 const float* __restrict__ beta) {
    int row = blockIdx.x;
    int t = threadIdx.x;
    float4 v = ((const float4*)(x + (size_t)row * DIM))[t];
    float s  = v.x + v.y + v.z + v.w;
    float ss = v.x * v.x + v.y * v.y + v.z * v.z + v.w * v.w;
#pragma unroll
    for (int o = 16; o > 0; o >>= 1) {
        s  += __shfl_xor_sync(0xffffffff, s, o);
        ss += __shfl_xor_sync(0xffffffff, ss, o);
    }
    __shared__ float sh_s[4], sh_ss[4];
    int w = t >> 5;
    if ((t & 31) == 0) { sh_s[w] = s; sh_ss[w] = ss; }
    __syncthreads();
    s  = sh_s[0] + sh_s[1] + sh_s[2] + sh_s[3];
    ss = sh_ss[0] + sh_ss[1] + sh_ss[2] + sh_ss[3];
    float mean = s * (1.0f / DIM);
    float var  = ss * (1.0f / DIM) - mean * mean;
    float inv  = rsqrtf(var + EPS);
    float4 g  = ((const float4*)gamma)[t];
    float4 bb = ((const float4*)beta)[t];
    float4 o4;
    o4.x = (v.x - mean) * inv * g.x + bb.x;
    o4.y = (v.y - mean) * inv * g.y + bb.y;
    o4.z = (v.z - mean) * inv * g.z + bb.z;
    o4.w = (v.w - mean) * inv * g.w + bb.w;
    ((float4*)(g_xn + (size_t)row * DIM))[t] = o4;
}

// ---------------------------------------------------------------------------
// GEMM: C[M,512] = A[M,512] @ W[512,512]^T   (both K-contiguous row-major)
// BM=BN=64, BK=16, 256 threads, 4x4 micro-tile per thread.
// ---------------------------------------------------------------------------
__global__ __launch_bounds__(256) void gemm_kernel(const float* __restrict__ A,
                                                   const float* __restrict__ W,
                                                   float* __restrict__ C) {
    const int K = DIM, N = DIM;
    __shared__ float As[16][64];
    __shared__ float Ws[16][64];
    int tx = threadIdx.x, ty = threadIdx.y;
    int tid = ty * 16 + tx;
    int m0 = blockIdx.y * 64, n0 = blockIdx.x * 64;
    int li = tid >> 2;          // 0..63: tile row
    int lk = (tid & 3) * 4;     // 0,4,8,12: k offset

    float acc[4][4] = {};
    const float* Ap = A + (size_t)(m0 + li) * K + lk;
    const float* Wp = W + (size_t)(n0 + li) * K + lk;

    for (int k0 = 0; k0 < K; k0 += 16) {
        float4 a = *(const float4*)(Ap + k0);
        float4 w = *(const float4*)(Wp + k0);
        As[lk + 0][li] = a.x; As[lk + 1][li] = a.y; As[lk + 2][li] = a.z; As[lk + 3][li] = a.w;
        Ws[lk + 0][li] = w.x; Ws[lk + 1][li] = w.y; Ws[lk + 2][li] = w.z; Ws[lk + 3][li] = w.w;
        __syncthreads();
#pragma unroll
        for (int kk = 0; kk < 16; kk++) {
            float4 av = *(const float4*)&As[kk][ty * 4];
            float4 wv = *(const float4*)&Ws[kk][tx * 4];
            float ar[4] = {av.x, av.y, av.z, av.w};
            float wr[4] = {wv.x, wv.y, wv.z, wv.w};
#pragma unroll
            for (int r = 0; r < 4; r++)
#pragma unroll
                for (int c = 0; c < 4; c++)
                    acc[r][c] += ar[r] * wr[c];
        }
        __syncthreads();
    }
#pragma unroll
    for (int r = 0; r < 4; r++) {
        float4 o4 = make_float4(acc[r][0], acc[r][1], acc[r][2], acc[r][3]);
        *(float4*)(C + (size_t)(m0 + ty * 4 + r) * N + n0 + tx * 4) = o4;
    }
}

// ---------------------------------------------------------------------------
// Flash attention: each thread owns ONE query row (softmax is thread-local).
// CTA = 128 threads = 128 queries of one (b,h). Stream K/V in 32-key tiles
// through shared memory (broadcast reads, conflict-free).
// ---------------------------------------------------------------------------
__global__ __launch_bounds__(128) void attn_kernel() {
    int b = blockIdx.z, h = blockIdx.y;
    int qi = blockIdx.x * 128 + threadIdx.x;

    const float* qp = g_q + ((size_t)(b * S + qi)) * DIM + h * HD;
    float q[HD];
#pragma unroll
    for (int d4 = 0; d4 < HD / 4; d4++) {
        float4 t = *(const float4*)(qp + d4 * 4);
        q[d4 * 4 + 0] = t.x * SCALE;
        q[d4 * 4 + 1] = t.y * SCALE;
        q[d4 * 4 + 2] = t.z * SCALE;
        q[d4 * 4 + 3] = t.w * SCALE;
    }

    float o[HD] = {};
    float m = -1e30f, l = 0.0f;

    __shared__ float Ks[32][64];
    __shared__ float Vs[32][64];
    const float* kbase = g_k + ((size_t)b * S) * DIM + h * HD;
    const float* vbase = g_v + ((size_t)b * S) * DIM + h * HD;

    for (int kt = 0; kt < S; kt += 32) {
#pragma unroll
        for (int r = 0; r < 4; r++) {
            int idx = threadIdx.x + 128 * r;   // 0..511 float4 slots
            int j = idx >> 4;
            int dd = (idx & 15) << 2;
            *(float4*)&Ks[j][dd] = *(const float4*)(kbase + (size_t)(kt + j) * DIM + dd);
            *(float4*)&Vs[j][dd] = *(const float4*)(vbase + (size_t)(kt + j) * DIM + dd);
        }
        __syncthreads();

        float sc[32];
        float tmax = -1e30f;
#pragma unroll
        for (int j = 0; j < 32; j++) {
            float s = 0.0f;
#pragma unroll
            for (int d4 = 0; d4 < 16; d4++) {
                float4 kv = *(const float4*)&Ks[j][d4 * 4];
                s += q[d4 * 4 + 0] * kv.x + q[d4 * 4 + 1] * kv.y
                   + q[d4 * 4 + 2] * kv.z + q[d4 * 4 + 3] * kv.w;
            }
            sc[j] = s;
            tmax = fmaxf(tmax, s);
        }

        float mnew = fmaxf(m, tmax);
        float alpha = __expf(m - mnew);
        l *= alpha;
#pragma unroll
        for (int d = 0; d < HD; d++) o[d] *= alpha;

#pragma unroll
        for (int j = 0; j < 32; j++) {
            float p = __expf(sc[j] - mnew);
            l += p;
#pragma unroll
            for (int d4 = 0; d4 < 16; d4++) {
                float4 vv = *(const float4*)&Vs[j][d4 * 4];
                o[d4 * 4 + 0] += p * vv.x;
                o[d4 * 4 + 1] += p * vv.y;
                o[d4 * 4 + 2] += p * vv.z;
                o[d4 * 4 + 3] += p * vv.w;
            }
        }
        m = mnew;
        __syncthreads();
    }

    float inv = 1.0f / l;
    float* op = g_att + ((size_t)(b * S + qi)) * DIM + h * HD;
#pragma unroll
    for (int d4 = 0; d4 < 16; d4++) {
        float4 t;
        t.x = o[d4 * 4 + 0] * inv;
        t.y = o[d4 * 4 + 1] * inv;
        t.z = o[d4 * 4 + 2] * inv;
        t.w = o[d4 * 4 + 3] * inv;
        *(float4*)(op + d4 * 4) = t;
    }
}

// ---------------------------------------------------------------------------
extern "C" void kernel_launch(void* const* d_in, const int* in_sizes, int n_in,
                              void* d_out, int out_size) {
    const float* x     = (const float*)d_in[0];
    const float* gamma = (const float*)d_in[1];
    const float* beta  = (const float*)d_in[2];
    const float* wq    = (const float*)d_in[3];
    const float* wk    = (const float*)d_in[4];
    const float* wv    = (const float*)d_in[5];
    const float* wfc   = (const float*)d_in[6];
    float* out = (float*)d_out;

    float *xn, *qb, *kb, *vb, *att;
    cudaGetSymbolAddress((void**)&xn,  g_xn);
    cudaGetSymbolAddress((void**)&qb,  g_q);
    cudaGetSymbolAddress((void**)&kb,  g_k);
    cudaGetSymbolAddress((void**)&vb,  g_v);
    cudaGetSymbolAddress((void**)&att, g_att);

    ln_kernel<<<B * S, 128>>>(x, gamma, beta);

    dim3 gb(16, 16);
    dim3 gg(DIM / 64, (B * S) / 64);
    gemm_kernel<<<gg, gb>>>(xn, wq, qb);
    gemm_kernel<<<gg, gb>>>(xn, wk, kb);
    gemm_kernel<<<gg, gb>>>(xn, wv, vb);

    attn_kernel<<<dim3(S / 128, H, B), 128>>>();

    gemm_kernel<<<gg, gb>>>(att, wfc, out);
}

// round 2
// speedup vs baseline: 3.1318x; 3.1318x over previous
#include <cuda_runtime.h>
#include <cuda_bf16.h>

#define B 2
#define S 4096
#define DIM 512
#define H 8
#define HD 64

static constexpr float SCALE = 0.125f;   // HD^-0.5
static constexpr float EPS = 1e-5f;
static constexpr float LOG2E = 1.4426950408889634f;

// Scratch (__device__ globals per allocation-free rule)
__device__ float g_xn[B * S * DIM];
__device__ float g_q[B * S * DIM];
__device__ float g_k[B * S * DIM];
__device__ float g_v[B * S * DIM];
__device__ float g_att[B * S * DIM];
__device__ float g_wq[DIM * DIM];
__device__ float g_wk[DIM * DIM];
__device__ float g_wv[DIM * DIM];
__device__ float g_wfc[DIM * DIM];

// ---------------------------------------------------------------------------
// helpers
// ---------------------------------------------------------------------------
__device__ __forceinline__ float tf32r(float x) {
    unsigned u;
    asm("cvt.rna.tf32.f32 %0, %1;" : "=r"(u) : "f"(x));
    return __uint_as_float(u);
}

__device__ __forceinline__ void mma8(float* c, const unsigned* a, const unsigned* b) {
    asm volatile(
        "mma.sync.aligned.m16n8k8.row.col.f32.tf32.tf32.f32 "
        "{%0,%1,%2,%3},{%4,%5,%6,%7},{%8,%9},{%0,%1,%2,%3};"
        : "+f"(c[0]), "+f"(c[1]), "+f"(c[2]), "+f"(c[3])
        : "r"(a[0]), "r"(a[1]), "r"(a[2]), "r"(a[3]), "r"(b[0]), "r"(b[1]));
}

// FFMA-pipe exp2 (no MUFU): floor-split + deg-4 poly, rel err ~2e-5
__device__ __forceinline__ float exp2fast(float x) {
    x = fmaxf(x, -126.0f);
    float n = floorf(x);
    float f = x - n;
    float p = 1.0f + f * (0.69314718f + f * (0.24022651f + f * (0.05550411f + f * 0.00898934f)));
    return __uint_as_float(__float_as_uint(p) + (((int)n) << 23));
}

// ---------------------------------------------------------------------------
// LayerNorm: one block per row, output pre-rounded to tf32
// ---------------------------------------------------------------------------
__global__ __launch_bounds__(128) void ln_kernel(const float* __restrict__ x,
                                                 const float* __restrict__ gamma,
                                                 const float* __restrict__ beta) {
    int row = blockIdx.x;
    int t = threadIdx.x;
    float4 v = ((const float4*)(x + (size_t)row * DIM))[t];
    float s  = v.x + v.y + v.z + v.w;
    float ss = v.x * v.x + v.y * v.y + v.z * v.z + v.w * v.w;
#pragma unroll
    for (int o = 16; o > 0; o >>= 1) {
        s  += __shfl_xor_sync(0xffffffff, s, o);
        ss += __shfl_xor_sync(0xffffffff, ss, o);
    }
    __shared__ float sh_s[4], sh_ss[4];
    int w = t >> 5;
    if ((t & 31) == 0) { sh_s[w] = s; sh_ss[w] = ss; }
    __syncthreads();
    s  = sh_s[0] + sh_s[1] + sh_s[2] + sh_s[3];
    ss = sh_ss[0] + sh_ss[1] + sh_ss[2] + sh_ss[3];
    float mean = s * (1.0f / DIM);
    float var  = ss * (1.0f / DIM) - mean * mean;
    float inv  = rsqrtf(var + EPS);
    float4 g  = ((const float4*)gamma)[t];
    float4 bb = ((const float4*)beta)[t];
    float4 o4;
    o4.x = tf32r((v.x - mean) * inv * g.x + bb.x);
    o4.y = tf32r((v.y - mean) * inv * g.y + bb.y);
    o4.z = tf32r((v.z - mean) * inv * g.z + bb.z);
    o4.w = tf32r((v.w - mean) * inv * g.w + bb.w);
    ((float4*)(g_xn + (size_t)row * DIM))[t] = o4;
}

// ---------------------------------------------------------------------------
// Pre-round the 4 weight matrices to tf32 (so GEMM inner loops need no cvt)
// ---------------------------------------------------------------------------
__device__ __forceinline__ float4 round4(float4 v) {
    v.x = tf32r(v.x); v.y = tf32r(v.y); v.z = tf32r(v.z); v.w = tf32r(v.w);
    return v;
}
__global__ __launch_bounds__(256) void prep_w(const float* __restrict__ a, const float* __restrict__ b,
                                              const float* __restrict__ c, const float* __restrict__ d) {
    int i = blockIdx.x * blockDim.x + threadIdx.x;   // DIM*DIM/4 float4 slots
    ((float4*)g_wq)[i]  = round4(((const float4*)a)[i]);
    ((float4*)g_wk)[i]  = round4(((const float4*)b)[i]);
    ((float4*)g_wv)[i]  = round4(((const float4*)c)[i]);
    ((float4*)g_wfc)[i] = round4(((const float4*)d)[i]);
}

// ---------------------------------------------------------------------------
// tf32 tensor-core GEMM: C[M,512] = A[M,512] @ W[512,512]^T
// CTA 64x64 tile, BK=32, 4 warps each 16x64, m16n8k8
// Operands A and W must already be tf32-rounded.
// ---------------------------------------------------------------------------
__global__ __launch_bounds__(128) void gemm_tc(const float* __restrict__ A,
                                               const float* __restrict__ W,
                                               float* __restrict__ C,
                                               float outScale, int doRound) {
    __shared__ float As[64][36];   // stride 36: conflict-free frag loads, 16B-aligned
    __shared__ float Ws[64][36];
    int tid = threadIdx.x, lane = tid & 31, w = tid >> 5;
    int g = lane >> 2, tg = lane & 3;
    int m0 = blockIdx.y * 64, n0 = blockIdx.x * 64;

    float acc[8][4] = {};

    int lr = tid >> 3;            // 0..15
    int lc = (tid & 7) * 4;       // 0..28
    const float* Ap = A + (size_t)(m0 + lr) * DIM + lc;
    const float* Wp = W + (size_t)(n0 + lr) * DIM + lc;

    for (int k0 = 0; k0 < DIM; k0 += 32) {
#pragma unroll
        for (int i = 0; i < 4; i++) {
            *(float4*)&As[lr + 16 * i][lc] = *(const float4*)(Ap + (size_t)(16 * i) * DIM + k0);
            *(float4*)&Ws[lr + 16 * i][lc] = *(const float4*)(Wp + (size_t)(16 * i) * DIM + k0);
        }
        __syncthreads();
#pragma unroll
        for (int ks = 0; ks < 4; ks++) {
            unsigned af[4];
            af[0] = __float_as_uint(As[w * 16 + g][ks * 8 + tg]);
            af[1] = __float_as_uint(As[w * 16 + g + 8][ks * 8 + tg]);
            af[2] = __float_as_uint(As[w * 16 + g][ks * 8 + tg + 4]);
            af[3] = __float_as_uint(As[w * 16 + g + 8][ks * 8 + tg + 4]);
#pragma unroll
            for (int nt = 0; nt < 8; nt++) {
                unsigned bf[2];
                bf[0] = __float_as_uint(Ws[nt * 8 + g][ks * 8 + tg]);
                bf[1] = __float_as_uint(Ws[nt * 8 + g][ks * 8 + tg + 4]);
                mma8(acc[nt], af, bf);
            }
        }
        __syncthreads();
    }

    int mrow = m0 + w * 16 + g;
#pragma unroll
    for (int nt = 0; nt < 8; nt++) {
        int col = n0 + nt * 8 + tg * 2;
        float2 v0 = make_float2(acc[nt][0] * outScale, acc[nt][1] * outScale);
        float2 v1 = make_float2(acc[nt][2] * outScale, acc[nt][3] * outScale);
        if (doRound) {
            v0.x = tf32r(v0.x); v0.y = tf32r(v0.y);
            v1.x = tf32r(v1.x); v1.y = tf32r(v1.y);
        }
        *(float2*)(C + (size_t)mrow * DIM + col)       = v0;
        *(float2*)(C + (size_t)(mrow + 8) * DIM + col) = v1;
    }
}

// ---------------------------------------------------------------------------
// Tensor-core flash attention. CTA = 8 warps = 128 queries of one (b,h).
// Q prescaled by SCALE*log2e -> softmax in base-2 with FFMA exp2.
// K/V streamed in 64-key tiles. P via per-warp smem (layout change only).
// ---------------------------------------------------------------------------
#define KS_STRIDE 68
#define VS_STRIDE 72
#define PS_STRIDE 68
#define SMEM_ATTN ((64 * KS_STRIDE + 64 * VS_STRIDE + 8 * 16 * PS_STRIDE) * 4)

__global__ __launch_bounds__(256) void attn_tc() {
    extern __shared__ float sm[];
    float* Ks = sm;                                   // [64][68]
    float* Vs = sm + 64 * KS_STRIDE;                  // [64][72]
    float* Ps = sm + 64 * KS_STRIDE + 64 * VS_STRIDE; // 8 x [16][68]

    int tid = threadIdx.x, lane = tid & 31, w = tid >> 5;
    int g = lane >> 2, tg = lane & 3;
    int b = blockIdx.z, h = blockIdx.y;
    int q0 = blockIdx.x * 128;
    float* Pw = Ps + w * 16 * PS_STRIDE;

    // Stage this warp's 16 Q rows into its private P buffer, extract A-frags
    const float* qbase = g_q + ((size_t)(b * S + q0 + w * 16)) * DIM + h * HD;
#pragma unroll
    for (int i = 0; i < 8; i++) {
        int idx = lane + 32 * i;                      // 0..255 float4 slots
        int r = idx >> 4, c4 = (idx & 15) << 2;
        *(float4*)&Pw[r * PS_STRIDE + c4] = *(const float4*)(qbase + (size_t)r * DIM + c4);
    }
    __syncwarp();
    unsigned qf[8][4];
#pragma unroll
    for (int ks = 0; ks < 8; ks++) {
        qf[ks][0] = __float_as_uint(Pw[g * PS_STRIDE + ks * 8 + tg]);
        qf[ks][1] = __float_as_uint(Pw[(g + 8) * PS_STRIDE + ks * 8 + tg]);
        qf[ks][2] = __float_as_uint(Pw[g * PS_STRIDE + ks * 8 + tg + 4]);
        qf[ks][3] = __float_as_uint(Pw[(g + 8) * PS_STRIDE + ks * 8 + tg + 4]);
    }

    float O[8][4] = {};
    float m0r = -1e30f, m1r = -1e30f, l0 = 0.f, l1 = 0.f;

    const float* kbase = g_k + ((size_t)(b * S)) * DIM + h * HD;
    const float* vbase = g_v + ((size_t)(b * S)) * DIM + h * HD;

    for (int kt = 0; kt < S; kt += 64) {
        __syncthreads();  // previous tile fully consumed
#pragma unroll
        for (int i = 0; i < 4; i++) {
            int idx = tid + 256 * i;                  // 0..1023 float4 slots
            int r = idx >> 4, c4 = (idx & 15) << 2;
            *(float4*)&Ks[r * KS_STRIDE + c4] = *(const float4*)(kbase + (size_t)(kt + r) * DIM + c4);
            *(float4*)&Vs[r * VS_STRIDE + c4] = *(const float4*)(vbase + (size_t)(kt + r) * DIM + c4);
        }
        __syncthreads();

        // ---- S = Q K^T (base-2 logits; Q carries SCALE*log2e) ----
        float Sc[8][4] = {};
#pragma unroll
        for (int ks = 0; ks < 8; ks++) {
#pragma unroll
            for (int nt = 0; nt < 8; nt++) {
                unsigned bf[2];
                bf[0] = __float_as_uint(Ks[(nt * 8 + g) * KS_STRIDE + ks * 8 + tg]);
                bf[1] = __float_as_uint(Ks[(nt * 8 + g) * KS_STRIDE + ks * 8 + tg + 4]);
                mma8(Sc[nt], qf[ks], bf);
            }
        }

        // ---- online softmax (2 rows per thread: g and g+8) ----
        float mx0 = -1e30f, mx1 = -1e30f;
#pragma unroll
        for (int nt = 0; nt < 8; nt++) {
            mx0 = fmaxf(mx0, fmaxf(Sc[nt][0], Sc[nt][1]));
            mx1 = fmaxf(mx1, fmaxf(Sc[nt][2], Sc[nt][3]));
        }
        mx0 = fmaxf(mx0, __shfl_xor_sync(0xffffffff, mx0, 1));
        mx0 = fmaxf(mx0, __shfl_xor_sync(0xffffffff, mx0, 2));
        mx1 = fmaxf(mx1, __shfl_xor_sync(0xffffffff, mx1, 1));
        mx1 = fmaxf(mx1, __shfl_xor_sync(0xffffffff, mx1, 2));
        float mn0 = fmaxf(m0r, mx0), mn1 = fmaxf(m1r, mx1);
        float a0 = exp2fast(m0r - mn0), a1 = exp2fast(m1r - mn1);

        float rs0 = 0.f, rs1 = 0.f;
#pragma unroll
        for (int nt = 0; nt < 8; nt++) {
            Sc[nt][0] = exp2fast(Sc[nt][0] - mn0);
            Sc[nt][1] = exp2fast(Sc[nt][1] - mn0);
            Sc[nt][2] = exp2fast(Sc[nt][2] - mn1);
            Sc[nt][3] = exp2fast(Sc[nt][3] - mn1);
            rs0 += Sc[nt][0] + Sc[nt][1];
            rs1 += Sc[nt][2] + Sc[nt][3];
        }
        rs0 += __shfl_xor_sync(0xffffffff, rs0, 1);
        rs0 += __shfl_xor_sync(0xffffffff, rs0, 2);
        rs1 += __shfl_xor_sync(0xffffffff, rs1, 1);
        rs1 += __shfl_xor_sync(0xffffffff, rs1, 2);
        l0 = l0 * a0 + rs0;
        l1 = l1 * a1 + rs1;
#pragma unroll
        for (int nt = 0; nt < 8; nt++) {
            O[nt][0] *= a0; O[nt][1] *= a0;
            O[nt][2] *= a1; O[nt][3] *= a1;
        }
        m0r = mn0; m1r = mn1;

        // ---- P -> per-warp smem (tf32-rounded), reload as A-frags ----
#pragma unroll
        for (int nt = 0; nt < 8; nt++) {
            *(float2*)&Pw[g * PS_STRIDE + nt * 8 + tg * 2] =
                make_float2(tf32r(Sc[nt][0]), tf32r(Sc[nt][1]));
            *(float2*)&Pw[(g + 8) * PS_STRIDE + nt * 8 + tg * 2] =
                make_float2(tf32r(Sc[nt][2]), tf32r(Sc[nt][3]));
        }
        __syncwarp();

        // ---- O += P V ----
#pragma unroll
        for (int ks = 0; ks < 8; ks++) {
            unsigned af[4];
            af[0] = __float_as_uint(Pw[g * PS_STRIDE + ks * 8 + tg]);
            af[1] = __float_as_uint(Pw[(g + 8) * PS_STRIDE + ks * 8 + tg]);
            af[2] = __float_as_uint(Pw[g * PS_STRIDE + ks * 8 + tg + 4]);
            af[3] = __float_as_uint(Pw[(g + 8) * PS_STRIDE + ks * 8 + tg + 4]);
#pragma unroll
            for (int nt = 0; nt < 8; nt++) {
                unsigned bf[2];
                bf[0] = __float_as_uint(Vs[(ks * 8 + tg) * VS_STRIDE + nt * 8 + g]);
                bf[1] = __float_as_uint(Vs[(ks * 8 + tg + 4) * VS_STRIDE + nt * 8 + g]);
                mma8(O[nt], af, bf);
            }
        }
    }

    // ---- normalize + store (tf32-rounded for final projection) ----
    float i0 = 1.f / l0, i1 = 1.f / l1;
    float* obase = g_att + ((size_t)(b * S + q0 + w * 16)) * DIM + h * HD;
#pragma unroll
    for (int nt = 0; nt < 8; nt++) {
        int col = nt * 8 + tg * 2;
        *(float2*)(obase + (size_t)g * DIM + col) =
            make_float2(tf32r(O[nt][0] * i0), tf32r(O[nt][1] * i0));
        *(float2*)(obase + (size_t)(g + 8) * DIM + col) =
            make_float2(tf32r(O[nt][2] * i1), tf32r(O[nt][3] * i1));
    }
}

// ---------------------------------------------------------------------------
extern "C" void kernel_launch(void* const* d_in, const int* in_sizes, int n_in,
                              void* d_out, int out_size) {
    const float* x     = (const float*)d_in[0];
    const float* gamma = (const float*)d_in[1];
    const float* beta  = (const float*)d_in[2];
    const float* wq    = (const float*)d_in[3];
    const float* wk    = (const float*)d_in[4];
    const float* wv    = (const float*)d_in[5];
    const float* wfc   = (const float*)d_in[6];
    float* out = (float*)d_out;

    float *xn, *qb, *kb, *vb, *att, *pwq, *pwk, *pwv, *pwfc;
    cudaGetSymbolAddress((void**)&xn,   g_xn);
    cudaGetSymbolAddress((void**)&qb,   g_q);
    cudaGetSymbolAddress((void**)&kb,   g_k);
    cudaGetSymbolAddress((void**)&vb,   g_v);
    cudaGetSymbolAddress((void**)&att,  g_att);
    cudaGetSymbolAddress((void**)&pwq,  g_wq);
    cudaGetSymbolAddress((void**)&pwk,  g_wk);
    cudaGetSymbolAddress((void**)&pwv,  g_wv);
    cudaGetSymbolAddress((void**)&pwfc, g_wfc);

    static bool attr_set = false;
    if (!attr_set) {
        cudaFuncSetAttribute(attn_tc, cudaFuncAttributeMaxDynamicSharedMemorySize, SMEM_ATTN);
        attr_set = true;
    }

    ln_kernel<<<B * S, 128>>>(x, gamma, beta);
    prep_w<<<DIM * DIM / 4 / 256, 256>>>(wq, wk, wv, wfc);

    dim3 gg(DIM / 64, (B * S) / 64);
    gemm_tc<<<gg, 128>>>(xn, pwq, qb, SCALE * LOG2E, 1);  // Q pre-scaled to base-2 domain
    gemm_tc<<<gg, 128>>>(xn, pwk, kb, 1.0f, 1);
    gemm_tc<<<gg, 128>>>(xn, pwv, vb, 1.0f, 1);

    attn_tc<<<dim3(S / 128, H, B), 256, SMEM_ATTN>>>();

    gemm_tc<<<gg, 128>>>(att, pwfc, out, 1.0f, 0);        // final projection, fp32 out
}

// round 3
// speedup vs baseline: 3.5360x; 1.1291x over previous
#include <cuda_runtime.h>
#include <cuda_bf16.h>

#define B 2
#define S 4096
#define DIM 512
#define H 8
#define HD 64

static constexpr float SCALE = 0.125f;   // HD^-0.5
static constexpr float EPS = 1e-5f;
static constexpr float LOG2E = 1.4426950408889634f;

// Scratch (__device__ globals per allocation-free rule)
__device__ float g_xn[B * S * DIM];
__device__ float g_q[B * S * DIM];
__device__ float g_k[B * S * DIM];
__device__ float g_v[B * S * DIM];
__device__ float g_att[B * S * DIM];
__device__ float g_wq[DIM * DIM];
__device__ float g_wk[DIM * DIM];
__device__ float g_wv[DIM * DIM];
__device__ float g_wfc[DIM * DIM];

// ---------------------------------------------------------------------------
// helpers
// ---------------------------------------------------------------------------
__device__ __forceinline__ float tf32r(float x) {
    unsigned u;
    asm("cvt.rna.tf32.f32 %0, %1;" : "=r"(u) : "f"(x));
    return __uint_as_float(u);
}

__device__ __forceinline__ void mma8(float* c, const unsigned* a, const unsigned* b) {
    asm volatile(
        "mma.sync.aligned.m16n8k8.row.col.f32.tf32.tf32.f32 "
        "{%0,%1,%2,%3},{%4,%5,%6,%7},{%8,%9},{%0,%1,%2,%3};"
        : "+f"(c[0]), "+f"(c[1]), "+f"(c[2]), "+f"(c[3])
        : "r"(a[0]), "r"(a[1]), "r"(a[2]), "r"(a[3]), "r"(b[0]), "r"(b[1]));
}

// FFMA-pipe exp2 (no MUFU): floor-split + deg-4 poly
__device__ __forceinline__ float exp2fast(float x) {
    x = fmaxf(x, -126.0f);
    float n = floorf(x);
    float f = x - n;
    float p = 1.0f + f * (0.69314718f + f * (0.24022651f + f * (0.05550411f + f * 0.00898934f)));
    return __uint_as_float(__float_as_uint(p) + (((int)n) << 23));
}

__device__ __forceinline__ void cpa16(void* dst, const void* src) {
    unsigned d = (unsigned)__cvta_generic_to_shared(dst);
    asm volatile("cp.async.cg.shared.global [%0], [%1], 16;" :: "r"(d), "l"(src));
}
#define CP_COMMIT asm volatile("cp.async.commit_group;")
#define CP_WAIT1  asm volatile("cp.async.wait_group 1;")

// ---------------------------------------------------------------------------
// LayerNorm: one block per row, output pre-rounded to tf32
// ---------------------------------------------------------------------------
__global__ __launch_bounds__(128) void ln_kernel(const float* __restrict__ x,
                                                 const float* __restrict__ gamma,
                                                 const float* __restrict__ beta) {
    int row = blockIdx.x;
    int t = threadIdx.x;
    float4 v = ((const float4*)(x + (size_t)row * DIM))[t];
    float s  = v.x + v.y + v.z + v.w;
    float ss = v.x * v.x + v.y * v.y + v.z * v.z + v.w * v.w;
#pragma unroll
    for (int o = 16; o > 0; o >>= 1) {
        s  += __shfl_xor_sync(0xffffffff, s, o);
        ss += __shfl_xor_sync(0xffffffff, ss, o);
    }
    __shared__ float sh_s[4], sh_ss[4];
    int w = t >> 5;
    if ((t & 31) == 0) { sh_s[w] = s; sh_ss[w] = ss; }
    __syncthreads();
    s  = sh_s[0] + sh_s[1] + sh_s[2] + sh_s[3];
    ss = sh_ss[0] + sh_ss[1] + sh_ss[2] + sh_ss[3];
    float mean = s * (1.0f / DIM);
    float var  = ss * (1.0f / DIM) - mean * mean;
    float inv  = rsqrtf(var + EPS);
    float4 g  = ((const float4*)gamma)[t];
    float4 bb = ((const float4*)beta)[t];
    float4 o4;
    o4.x = tf32r((v.x - mean) * inv * g.x + bb.x);
    o4.y = tf32r((v.y - mean) * inv * g.y + bb.y);
    o4.z = tf32r((v.z - mean) * inv * g.z + bb.z);
    o4.w = tf32r((v.w - mean) * inv * g.w + bb.w);
    ((float4*)(g_xn + (size_t)row * DIM))[t] = o4;
}

// ---------------------------------------------------------------------------
// Pre-round the 4 weight matrices to tf32
// ---------------------------------------------------------------------------
__device__ __forceinline__ float4 round4(float4 v) {
    v.x = tf32r(v.x); v.y = tf32r(v.y); v.z = tf32r(v.z); v.w = tf32r(v.w);
    return v;
}
__global__ __launch_bounds__(256) void prep_w(const float* __restrict__ a, const float* __restrict__ b,
                                              const float* __restrict__ c, const float* __restrict__ d) {
    int i = blockIdx.x * blockDim.x + threadIdx.x;
    ((float4*)g_wq)[i]  = round4(((const float4*)a)[i]);
    ((float4*)g_wk)[i]  = round4(((const float4*)b)[i]);
    ((float4*)g_wv)[i]  = round4(((const float4*)c)[i]);
    ((float4*)g_wfc)[i] = round4(((const float4*)d)[i]);
}

// ---------------------------------------------------------------------------
// tf32 tensor-core GEMM, cp.async double-buffered.
// C[M,512] = A[M,512] @ W[512,512]^T. 64x64 CTA tile, BK=32, 4 warps.
// k-permuted frag mapping: logical j -> physical 8ks + 2(j&3) + (j>>2),
// applied identically to A and W so all frag loads are LDS.64.
// ---------------------------------------------------------------------------
#define GS 40   // smem row stride (floats): conflict-free LDS.64 + cp.async STS

__global__ __launch_bounds__(128) void gemm_tc(const float* __restrict__ A,
                                               const float* __restrict__ W,
                                               float* __restrict__ C,
                                               float outScale, int doRound) {
    __shared__ float As[2][64][GS];
    __shared__ float Ws[2][64][GS];
    int tid = threadIdx.x, lane = tid & 31, w = tid >> 5;
    int g = lane >> 2, tg = lane & 3;
    int m0 = blockIdx.y * 64, n0 = blockIdx.x * 64;
    int lr = tid >> 3;            // 0..15
    int lc = (tid & 7) * 4;       // 0..28
    const float* Ap = A + (size_t)(m0 + lr) * DIM + lc;
    const float* Wp = W + (size_t)(n0 + lr) * DIM + lc;

    float acc[8][4] = {};

#pragma unroll
    for (int pf = 0; pf < 2; pf++) {
#pragma unroll
        for (int i = 0; i < 4; i++) {
            cpa16(&As[pf][lr + 16 * i][lc], Ap + (size_t)(16 * i) * DIM + 32 * pf);
            cpa16(&Ws[pf][lr + 16 * i][lc], Wp + (size_t)(16 * i) * DIM + 32 * pf);
        }
        CP_COMMIT;
    }

    for (int k0 = 0; k0 < DIM; k0 += 32) {
        int buf = (k0 >> 5) & 1;
        CP_WAIT1;
        __syncthreads();
#pragma unroll
        for (int ks = 0; ks < 4; ks++) {
            float2 a0 = *(const float2*)&As[buf][w * 16 + g][ks * 8 + 2 * tg];
            float2 a1 = *(const float2*)&As[buf][w * 16 + g + 8][ks * 8 + 2 * tg];
            unsigned af[4] = {__float_as_uint(a0.x), __float_as_uint(a1.x),
                              __float_as_uint(a0.y), __float_as_uint(a1.y)};
#pragma unroll
            for (int nt = 0; nt < 8; nt++) {
                float2 bv = *(const float2*)&Ws[buf][nt * 8 + g][ks * 8 + 2 * tg];
                unsigned bf[2] = {__float_as_uint(bv.x), __float_as_uint(bv.y)};
                mma8(acc[nt], af, bf);
            }
        }
        __syncthreads();
        if (k0 + 64 < DIM) {
#pragma unroll
            for (int i = 0; i < 4; i++) {
                cpa16(&As[buf][lr + 16 * i][lc], Ap + (size_t)(16 * i) * DIM + k0 + 64);
                cpa16(&Ws[buf][lr + 16 * i][lc], Wp + (size_t)(16 * i) * DIM + k0 + 64);
            }
        }
        CP_COMMIT;   // empty group past the end keeps wait-count exact
    }

    int mrow = m0 + w * 16 + g;
#pragma unroll
    for (int nt = 0; nt < 8; nt++) {
        int col = n0 + nt * 8 + tg * 2;
        float2 v0 = make_float2(acc[nt][0] * outScale, acc[nt][1] * outScale);
        float2 v1 = make_float2(acc[nt][2] * outScale, acc[nt][3] * outScale);
        if (doRound) {
            v0.x = tf32r(v0.x); v0.y = tf32r(v0.y);
            v1.x = tf32r(v1.x); v1.y = tf32r(v1.y);
        }
        *(float2*)(C + (size_t)mrow * DIM + col)       = v0;
        *(float2*)(C + (size_t)(mrow + 8) * DIM + col) = v1;
    }
}

// ---------------------------------------------------------------------------
// Tensor-core flash attention, cp.async double-buffered K/V, P in registers.
// CTA = 8 warps = 128 queries of one (b,h). Q carries SCALE*log2e (base-2).
// S-phase k-dim and PV k-dim both use the 8ks+2(j&3)+(j>>2) permutation:
//  - Q/K frags become LDS.64 / LDG.64
//  - the S-phase C-fragment IS the PV A-fragment (no smem P, no shuffle)
// ---------------------------------------------------------------------------
#define KSTR 72
#define VSTR 68
#define SMEM_ATTN ((2 * 64 * KSTR + 2 * 64 * VSTR) * 4)

__global__ __launch_bounds__(256) void attn_tc() {
    extern __shared__ float sm[];
    float* KsB[2] = {sm, sm + 64 * KSTR};
    float* VsB[2] = {sm + 2 * 64 * KSTR, sm + 2 * 64 * KSTR + 64 * VSTR};

    int tid = threadIdx.x, lane = tid & 31, w = tid >> 5;
    int g = lane >> 2, tg = lane & 3;
    int b = blockIdx.z, h = blockIdx.y;
    int q0 = blockIdx.x * 128;

    // Q A-frags straight from gmem (LDG.64, permuted k mapping)
    const float* qbase = g_q + ((size_t)(b * S + q0 + w * 16)) * DIM + h * HD;
    unsigned qf[8][4];
#pragma unroll
    for (int ks = 0; ks < 8; ks++) {
        float2 a0 = *(const float2*)(qbase + (size_t)g * DIM + ks * 8 + 2 * tg);
        float2 a1 = *(const float2*)(qbase + (size_t)(g + 8) * DIM + ks * 8 + 2 * tg);
        qf[ks][0] = __float_as_uint(a0.x);
        qf[ks][1] = __float_as_uint(a1.x);
        qf[ks][2] = __float_as_uint(a0.y);
        qf[ks][3] = __float_as_uint(a1.y);
    }

    const float* kbase = g_k + ((size_t)b * S) * DIM + h * HD;
    const float* vbase = g_v + ((size_t)b * S) * DIM + h * HD;

    // per-thread load slots: 4 float4 for K, 4 for V per tile
    int rl[4], cl[4];
#pragma unroll
    for (int i = 0; i < 4; i++) {
        int idx = tid + 256 * i;
        rl[i] = idx >> 4;
        cl[i] = (idx & 15) * 4;
    }

    // prefetch tiles 0,1
#pragma unroll
    for (int pf = 0; pf < 2; pf++) {
#pragma unroll
        for (int i = 0; i < 4; i++) {
            cpa16(&KsB[pf][rl[i] * KSTR + cl[i]], kbase + (size_t)(pf * 64 + rl[i]) * DIM + cl[i]);
            cpa16(&VsB[pf][rl[i] * VSTR + cl[i]], vbase + (size_t)(pf * 64 + rl[i]) * DIM + cl[i]);
        }
        CP_COMMIT;
    }

    float O[8][4] = {};
    float m0r = -1e30f, m1r = -1e30f, l0 = 0.f, l1 = 0.f;

    for (int kt = 0; kt < S / 64; kt++) {
        int bufi = kt & 1;
        CP_WAIT1;
        __syncthreads();
        const float* Kb = KsB[bufi];
        const float* Vb = VsB[bufi];

        // ---- S = Q K^T ----
        float Sc[8][4] = {};
#pragma unroll
        for (int ks = 0; ks < 8; ks++) {
#pragma unroll
            for (int nt = 0; nt < 8; nt++) {
                float2 bv = *(const float2*)&Kb[(nt * 8 + g) * KSTR + ks * 8 + 2 * tg];
                unsigned bf[2] = {__float_as_uint(bv.x), __float_as_uint(bv.y)};
                mma8(Sc[nt], qf[ks], bf);
            }
        }

        // ---- online softmax (rows g and g+8) ----
        float mx0 = -1e30f, mx1 = -1e30f;
#pragma unroll
        for (int nt = 0; nt < 8; nt++) {
            mx0 = fmaxf(mx0, fmaxf(Sc[nt][0], Sc[nt][1]));
            mx1 = fmaxf(mx1, fmaxf(Sc[nt][2], Sc[nt][3]));
        }
        mx0 = fmaxf(mx0, __shfl_xor_sync(0xffffffff, mx0, 1));
        mx0 = fmaxf(mx0, __shfl_xor_sync(0xffffffff, mx0, 2));
        mx1 = fmaxf(mx1, __shfl_xor_sync(0xffffffff, mx1, 1));
        mx1 = fmaxf(mx1, __shfl_xor_sync(0xffffffff, mx1, 2));
        float mn0 = fmaxf(m0r, mx0), mn1 = fmaxf(m1r, mx1);
        float a0 = exp2fast(m0r - mn0), a1 = exp2fast(m1r - mn1);

        float rs0 = 0.f, rs1 = 0.f;
#pragma unroll
        for (int nt = 0; nt < 8; nt++) {
            Sc[nt][0] = exp2fast(Sc[nt][0] - mn0);
            Sc[nt][1] = exp2fast(Sc[nt][1] - mn0);
            Sc[nt][2] = exp2fast(Sc[nt][2] - mn1);
            Sc[nt][3] = exp2fast(Sc[nt][3] - mn1);
            rs0 += Sc[nt][0] + Sc[nt][1];
            rs1 += Sc[nt][2] + Sc[nt][3];
        }
        rs0 += __shfl_xor_sync(0xffffffff, rs0, 1);
        rs0 += __shfl_xor_sync(0xffffffff, rs0, 2);
        rs1 += __shfl_xor_sync(0xffffffff, rs1, 1);
        rs1 += __shfl_xor_sync(0xffffffff, rs1, 2);
        l0 = l0 * a0 + rs0;
        l1 = l1 * a1 + rs1;
#pragma unroll
        for (int nt = 0; nt < 8; nt++) {
            O[nt][0] *= a0; O[nt][1] *= a0;
            O[nt][2] *= a1; O[nt][3] *= a1;
        }
        m0r = mn0; m1r = mn1;

        // ---- O += P V : S-phase C-frag is directly the PV A-frag ----
#pragma unroll
        for (int ks = 0; ks < 8; ks++) {
            unsigned af[4];
            af[0] = __float_as_uint(tf32r(Sc[ks][0]));
            af[1] = __float_as_uint(tf32r(Sc[ks][2]));
            af[2] = __float_as_uint(tf32r(Sc[ks][1]));
            af[3] = __float_as_uint(tf32r(Sc[ks][3]));
#pragma unroll
            for (int nt = 0; nt < 8; nt++) {
                unsigned bf[2] = {
                    __float_as_uint(Vb[(ks * 8 + 2 * tg) * VSTR + nt * 8 + g]),
                    __float_as_uint(Vb[(ks * 8 + 2 * tg + 1) * VSTR + nt * 8 + g])};
                mma8(O[nt], af, bf);
            }
        }

        __syncthreads();
        if (kt + 2 < S / 64) {
#pragma unroll
            for (int i = 0; i < 4; i++) {
                cpa16(&KsB[bufi][rl[i] * KSTR + cl[i]],
                      kbase + (size_t)((kt + 2) * 64 + rl[i]) * DIM + cl[i]);
                cpa16(&VsB[bufi][rl[i] * VSTR + cl[i]],
                      vbase + (size_t)((kt + 2) * 64 + rl[i]) * DIM + cl[i]);
            }
        }
        CP_COMMIT;
    }

    // ---- normalize + store (tf32-rounded for final projection) ----
    float i0 = 1.f / l0, i1 = 1.f / l1;
    float* obase = g_att + ((size_t)(b * S + q0 + w * 16)) * DIM + h * HD;
#pragma unroll
    for (int nt = 0; nt < 8; nt++) {
        int col = nt * 8 + tg * 2;
        *(float2*)(obase + (size_t)g * DIM + col) =
            make_float2(tf32r(O[nt][0] * i0), tf32r(O[nt][1] * i0));
        *(float2*)(obase + (size_t)(g + 8) * DIM + col) =
            make_float2(tf32r(O[nt][2] * i1), tf32r(O[nt][3] * i1));
    }
}

// ---------------------------------------------------------------------------
extern "C" void kernel_launch(void* const* d_in, const int* in_sizes, int n_in,
                              void* d_out, int out_size) {
    const float* x     = (const float*)d_in[0];
    const float* gamma = (const float*)d_in[1];
    const float* beta  = (const float*)d_in[2];
    const float* wq    = (const float*)d_in[3];
    const float* wk    = (const float*)d_in[4];
    const float* wv    = (const float*)d_in[5];
    const float* wfc   = (const float*)d_in[6];
    float* out = (float*)d_out;

    float *xn, *qb, *kb, *vb, *att, *pwq, *pwk, *pwv, *pwfc;
    cudaGetSymbolAddress((void**)&xn,   g_xn);
    cudaGetSymbolAddress((void**)&qb,   g_q);
    cudaGetSymbolAddress((void**)&kb,   g_k);
    cudaGetSymbolAddress((void**)&vb,   g_v);
    cudaGetSymbolAddress((void**)&att,  g_att);
    cudaGetSymbolAddress((void**)&pwq,  g_wq);
    cudaGetSymbolAddress((void**)&pwk,  g_wk);
    cudaGetSymbolAddress((void**)&pwv,  g_wv);
    cudaGetSymbolAddress((void**)&pwfc, g_wfc);

    cudaFuncSetAttribute(attn_tc, cudaFuncAttributeMaxDynamicSharedMemorySize, SMEM_ATTN);

    ln_kernel<<<B * S, 128>>>(x, gamma, beta);
    prep_w<<<DIM * DIM / 4 / 256, 256>>>(wq, wk, wv, wfc);

    dim3 gg(DIM / 64, (B * S) / 64);
    gemm_tc<<<gg, 128>>>(xn, pwq, qb, SCALE * LOG2E, 1);  // Q pre-scaled to base-2 domain
    gemm_tc<<<gg, 128>>>(xn, pwk, kb, 1.0f, 1);
    gemm_tc<<<gg, 128>>>(xn, pwv, vb, 1.0f, 1);

    attn_tc<<<dim3(S / 128, H, B), 256, SMEM_ATTN>>>();

    gemm_tc<<<gg, 128>>>(att, pwfc, out, 1.0f, 0);        // final projection, fp32 out
}